// round 5
// baseline (speedup 1.0000x reference)
#include <cuda_runtime.h>
#include <math.h>

// ---------------------------------------------------------------------------
// Problem constants
// ---------------------------------------------------------------------------
#define BATCH   8
#define HH      112
#define CC      192
#define WS      7
#define SHIFT   3
#define NHD     6
#define HDIM    32
#define NTK     49            // WS*WS
#define NWIN    2048          // BATCH * 16 * 16
#define MROWS   100352        // NWIN * NTK
#define LTOK    12544         // HH*HH
#define HID     768           // 4*C
#define TOKF    19267584      // MROWS*CC (one activation slab, floats)
#define LOG100F 4.6051701859880914f

// ---------------------------------------------------------------------------
// Scratch: ONE static device slab, manually partitioned (allocation-free).
// Layout (float offsets):
//   [0*TOKF)            hwin      (dead after QKV)   -- aliased by attno
//   [1*TOKF .. 4*TOKF)  qkv q|k|v (q-slab dead after attn) -- q aliased by proj
//   [4*TOKF)            h1
//   [5*TOKF .. 9*TOKF)  mlp1 (MROWS*HID)
//   [9*TOKF)            mlp2
// total 10*TOKF floats = 771 MB -> with aliasing below actual distinct = 10 slabs.
// (attno := slab0, proj := slab1) keeps it at 10*TOKF = 735 MiB contiguous.
// ---------------------------------------------------------------------------
__device__ float g_scratch[10ull * TOKF];
__device__ float g_cpb[169 * NHD];
__device__ float g_rpb[NHD * NTK * NTK];

#define OFF_HWIN  (0ull * TOKF)
#define OFF_QKV   (1ull * TOKF)     // q,k,v contiguous: 3 slabs
#define OFF_ATTNO (0ull * TOKF)     // aliases hwin (dead)
#define OFF_PROJ  (1ull * TOKF)     // aliases q-slab (dead after attn)
#define OFF_H1    (4ull * TOKF)
#define OFF_MLP1  (5ull * TOKF)     // 4 slabs (MROWS*HID)
#define OFF_MLP2  (9ull * TOKF)

// ---------------------------------------------------------------------------
// CPB MLP: 169 relative offsets -> 16*sigmoid(relu(t@w0+b0)@w1)
// ---------------------------------------------------------------------------
__device__ __forceinline__ float rel_coord(int a) {
    float ch = (float)(a - (WS - 1));
    float t  = ch / (float)(WS - 1) * 8.0f;
    float v  = log2f(fabsf(t) + 1.0f) / log2f(8.0f);
    return (t > 0.f) ? v : ((t < 0.f) ? -v : 0.f);
}

__global__ void cpb_kernel(const float* __restrict__ w0, const float* __restrict__ b0,
                           const float* __restrict__ w1) {
    int idx = blockIdx.x * blockDim.x + threadIdx.x;
    if (idx >= 169 * NHD) return;
    int t = idx / NHD, h = idx % NHD;
    float c0 = rel_coord(t / 13);
    float c1 = rel_coord(t % 13);
    float s = 0.f;
    for (int j = 0; j < 512; ++j) {
        float hid = fmaf(c0, w0[j], fmaf(c1, w0[512 + j], b0[j]));
        hid = fmaxf(hid, 0.f);
        s = fmaf(hid, w1[j * NHD + h], s);
    }
    g_cpb[idx] = 16.0f / (1.0f + expf(-s));
}

__global__ void rpb_kernel() {
    int idx = blockIdx.x * blockDim.x + threadIdx.x;
    if (idx >= NHD * NTK * NTK) return;
    int h = idx / (NTK * NTK), e = idx % (NTK * NTK);
    int i = e / NTK, j = e % NTK;
    int r0 = i / WS - j / WS + (WS - 1);
    int r1 = i % WS - j % WS + (WS - 1);
    g_rpb[idx] = g_cpb[(r0 * 13 + r1) * NHD + h];
}

// ---------------------------------------------------------------------------
// Shift + window partition gather (float4 wide)
// ---------------------------------------------------------------------------
__global__ void gather_kernel(const float4* __restrict__ x, float4* __restrict__ hwin) {
    int idx = blockIdx.x * 256 + threadIdx.x;                 // over MROWS*48
    if (idx >= MROWS * 48) return;
    int m = idx / 48, c4 = idx % 48;
    int w = m / NTK, n = m % NTK;
    int b = w >> 8, widx = w & 255;
    int wh = widx >> 4, ww = widx & 15;
    int gh = wh * WS + n / WS + SHIFT; if (gh >= HH) gh -= HH;
    int gw = ww * WS + n % WS + SHIFT; if (gw >= HH) gw -= HH;
    hwin[idx] = x[((size_t)(b * LTOK + gh * HH + gw)) * 48 + c4];
}

// ---------------------------------------------------------------------------
// Generic SGEMM 128x64x8, 256 threads, TM=8 TN=4, 4 epilogues
// ---------------------------------------------------------------------------
#define GBM 128
#define GBN 64
#define GBK 8

enum { EPI_PLAIN = 0, EPI_GELU = 1, EPI_PROJ = 2, EPI_QKV = 3 };

__device__ __forceinline__ float gelu_tanh(float x) {
    float x3 = x * x * x;
    return 0.5f * x * (1.0f + tanhf(0.7978845608028654f * (x + 0.044715f * x3)));
}

template <int EPI>
__global__ __launch_bounds__(256) void gemm_kernel(
    const float* __restrict__ A, const float* __restrict__ Bm,
    const float* __restrict__ bias, float* __restrict__ Cout,
    int Nn, int K)
{
    __shared__ float As[GBK][GBM];
    __shared__ float Bs[GBK][GBN];

    int tid = threadIdx.x;
    int bm = blockIdx.y, bn = blockIdx.x;
    int ty = tid >> 4, tx = tid & 15;

    float acc[8][4];
#pragma unroll
    for (int i = 0; i < 8; ++i)
#pragma unroll
        for (int j = 0; j < 4; ++j) acc[i][j] = 0.f;

    const float* Aptr = A + (size_t)bm * GBM * K;
    const float* Bptr = Bm + (size_t)bn * GBN;
    int aRow = tid >> 1;
    int aCol = (tid & 1) * 4;

    for (int k0 = 0; k0 < K; k0 += GBK) {
        float4 av = *(const float4*)(Aptr + (size_t)aRow * K + k0 + aCol);
        As[aCol + 0][aRow] = av.x;
        As[aCol + 1][aRow] = av.y;
        As[aCol + 2][aRow] = av.z;
        As[aCol + 3][aRow] = av.w;
        if (tid < 128) {
            float4 bv = *(const float4*)(Bptr + (size_t)(k0 + (tid >> 4)) * Nn + ((tid & 15) << 2));
            *(float4*)&Bs[tid >> 4][(tid & 15) << 2] = bv;
        }
        __syncthreads();
#pragma unroll
        for (int kk = 0; kk < GBK; ++kk) {
            float4 a0 = *(float4*)&As[kk][ty * 8];
            float4 a1 = *(float4*)&As[kk][ty * 8 + 4];
            float4 b0 = *(float4*)&Bs[kk][tx * 4];
            float ra[8] = {a0.x, a0.y, a0.z, a0.w, a1.x, a1.y, a1.z, a1.w};
            float rb[4] = {b0.x, b0.y, b0.z, b0.w};
#pragma unroll
            for (int i = 0; i < 8; ++i)
#pragma unroll
                for (int j = 0; j < 4; ++j) acc[i][j] = fmaf(ra[i], rb[j], acc[i][j]);
        }
        __syncthreads();
    }

    int row0 = bm * GBM + ty * 8;
    int col0 = bn * GBN + tx * 4;
#pragma unroll
    for (int i = 0; i < 8; ++i) {
        int row = row0 + i;
#pragma unroll
        for (int j = 0; j < 4; ++j) {
            int col = col0 + j;
            float v = acc[i][j];
            if constexpr (EPI == EPI_PLAIN) {
                Cout[(size_t)row * Nn + col] = v + bias[col];
            } else if constexpr (EPI == EPI_GELU) {
                Cout[(size_t)row * Nn + col] = gelu_tanh(v + bias[col]);
            } else if constexpr (EPI == EPI_PROJ) {
                v += bias[col];
                int w = row / NTK, n = row % NTK;
                int b = w >> 8, widx = w & 255;
                int wh = widx >> 4, ww = widx & 15;
                int gh = wh * WS + n / WS + SHIFT; if (gh >= HH) gh -= HH;
                int gw = ww * WS + n % WS + SHIFT; if (gw >= HH) gw -= HH;
                Cout[((size_t)(b * LTOK + gh * HH + gw)) * CC + col] = v;
            } else {  // EPI_QKV: scatter to [win][head][n][d]
                if (bias) v += bias[col];
                int head = col >> 5, d = col & 31;
                int w = row / NTK, n = row % NTK;
                size_t off = (((size_t)w * NHD + head) * NTK + n) * HDIM + d;
                Cout[off] = v;
            }
        }
    }
}

// ---------------------------------------------------------------------------
// L2-normalize q,k rows (32 elems each) : 1 warp per row
// ---------------------------------------------------------------------------
__global__ void normqk_kernel(float* __restrict__ qk) {
    int row = blockIdx.x * 8 + (threadIdx.x >> 5);   // rows: 2 * NWIN*NHD*NTK
    int lane = threadIdx.x & 31;
    float* p = qk + (size_t)row * HDIM;
    float v = p[lane];
    float ss = v * v;
#pragma unroll
    for (int o = 16; o; o >>= 1) ss += __shfl_xor_sync(0xffffffffu, ss, o);
    float sc = 1.0f / fmaxf(sqrtf(ss), 1e-6f);
    p[lane] = v * sc;
}

// ---------------------------------------------------------------------------
// Attention: 1 block per (window, head). smem q/kT/v + scores; softmax; PV.
// ---------------------------------------------------------------------------
__global__ __launch_bounds__(256) void attn_kernel(
    const float* __restrict__ qkv, const float* __restrict__ logit_scale,
    float* __restrict__ out)
{
    __shared__ float sq[NTK * HDIM];      // 49x32
    __shared__ float skT[HDIM * 50];      // 32x49 (padded)
    __shared__ float sv[NTK * HDIM];
    __shared__ float sS[NTK * 50];        // 49x49 (padded)

    int bid = blockIdx.x;
    int w = bid / NHD, hd = bid % NHD;
    size_t base = ((size_t)w * NHD + hd) * (NTK * HDIM);
    const float* qp = qkv + base;
    const float* kp = qkv + (size_t)TOKF + base;
    const float* vp = qkv + 2ull * TOKF + base;

    int tid = threadIdx.x;
    for (int i = tid; i < NTK * HDIM; i += 256) {
        sq[i] = qp[i];
        sv[i] = vp[i];
        int r = i >> 5, t = i & 31;
        skT[t * 50 + r] = kp[i];
    }
    float scale = expf(fminf(logit_scale[hd], LOG100F));
    int widx = w & 255;
    int wh = widx >> 4, ww = widx & 15;
    __syncthreads();

    // scores + bias + mask (mask regions on UNSHIFTED coords: bounds 105, 109)
    for (int e = tid; e < NTK * NTK; e += 256) {
        int i = e / NTK, j = e % NTK;
        float s = 0.f;
#pragma unroll 8
        for (int t = 0; t < HDIM; ++t) s = fmaf(sq[i * HDIM + t], skT[t * 50 + j], s);
        int hi = wh * WS + i / WS, wi = ww * WS + i % WS;
        int hj = wh * WS + j / WS, wj = ww * WS + j % WS;
        int idi = (hi < 105 ? 0 : (hi < 109 ? 1 : 2)) * 3 + (wi < 105 ? 0 : (wi < 109 ? 1 : 2));
        int idj = (hj < 105 ? 0 : (hj < 109 ? 1 : 2)) * 3 + (wj < 105 ? 0 : (wj < 109 ? 1 : 2));
        s = fmaf(s, scale, g_rpb[hd * (NTK * NTK) + e]);
        if (idi != idj) s -= 100.0f;
        sS[i * 50 + j] = s;
    }
    __syncthreads();

    // softmax: 1 warp per row
    int wid = tid >> 5, lane = tid & 31;
    for (int r = wid; r < NTK; r += 8) {
        float v0 = sS[r * 50 + lane];
        float v1 = (lane + 32 < NTK) ? sS[r * 50 + lane + 32] : -3.4e38f;
        float m = fmaxf(v0, v1);
#pragma unroll
        for (int o = 16; o; o >>= 1) m = fmaxf(m, __shfl_xor_sync(0xffffffffu, m, o));
        float e0 = expf(v0 - m);
        float e1 = (lane + 32 < NTK) ? expf(v1 - m) : 0.f;
        float s = e0 + e1;
#pragma unroll
        for (int o = 16; o; o >>= 1) s += __shfl_xor_sync(0xffffffffu, s, o);
        float inv = 1.0f / s;
        sS[r * 50 + lane] = e0 * inv;
        if (lane + 32 < NTK) sS[r * 50 + lane + 32] = e1 * inv;
    }
    __syncthreads();

    // O = P @ V  -> merged-head layout (MROWS, 192)
    for (int e = tid; e < NTK * HDIM; e += 256) {
        int i = e >> 5, d = e & 31;
        float acc = 0.f;
#pragma unroll
        for (int j = 0; j < NTK; ++j) acc = fmaf(sS[i * 50 + j], sv[j * HDIM + d], acc);
        out[((size_t)w * NTK + i) * CC + hd * HDIM + d] = acc;
    }
}

// ---------------------------------------------------------------------------
// out = res + LayerNorm(v) * g + b   (1 warp / row of 192)
// ---------------------------------------------------------------------------
__global__ void ln_res_kernel(const float* __restrict__ res, const float* __restrict__ v,
                              const float* __restrict__ g, const float* __restrict__ bb,
                              float* __restrict__ out) {
    int row = blockIdx.x * 8 + (threadIdx.x >> 5);
    int lane = threadIdx.x & 31;
    const float* vp = v + (size_t)row * CC;
    float x[6];
    float s = 0.f;
#pragma unroll
    for (int t = 0; t < 6; ++t) { x[t] = vp[lane + 32 * t]; s += x[t]; }
#pragma unroll
    for (int o = 16; o; o >>= 1) s += __shfl_xor_sync(0xffffffffu, s, o);
    float mean = s * (1.0f / CC);
    float q = 0.f;
#pragma unroll
    for (int t = 0; t < 6; ++t) { float d = x[t] - mean; q += d * d; }
#pragma unroll
    for (int o = 16; o; o >>= 1) q += __shfl_xor_sync(0xffffffffu, q, o);
    float rstd = rsqrtf(q * (1.0f / CC) + 1e-5f);
#pragma unroll
    for (int t = 0; t < 6; ++t) {
        int c = lane + 32 * t;
        out[(size_t)row * CC + c] = res[(size_t)row * CC + c] + (x[t] - mean) * rstd * g[c] + bb[c];
    }
}

// ---------------------------------------------------------------------------
// Launch
// ---------------------------------------------------------------------------
extern "C" void kernel_launch(void* const* d_in, const int* in_sizes, int n_in,
                              void* d_out, int out_size) {
    const float* x      = (const float*)d_in[0];
    const float* q_w    = (const float*)d_in[1];
    const float* q_b    = (const float*)d_in[2];
    const float* k_w    = (const float*)d_in[3];
    const float* v_w    = (const float*)d_in[4];
    const float* v_b    = (const float*)d_in[5];
    const float* proj_w = (const float*)d_in[6];
    const float* proj_b = (const float*)d_in[7];
    const float* lscale = (const float*)d_in[8];
    const float* cpb_w0 = (const float*)d_in[9];
    const float* cpb_b0 = (const float*)d_in[10];
    const float* cpb_w1 = (const float*)d_in[11];
    const float* ln1_g  = (const float*)d_in[12];
    const float* ln1_b  = (const float*)d_in[13];
    const float* ln2_g  = (const float*)d_in[14];
    const float* ln2_b  = (const float*)d_in[15];
    const float* fc1_w  = (const float*)d_in[16];
    const float* fc1_b  = (const float*)d_in[17];
    const float* fc2_w  = (const float*)d_in[18];
    const float* fc2_b  = (const float*)d_in[19];
    float* out = (float*)d_out;

    void* p;
    cudaGetSymbolAddress(&p, g_scratch);
    float* sc    = (float*)p;
    float* hwin  = sc + OFF_HWIN;
    float* qkv   = sc + OFF_QKV;
    float* attno = sc + OFF_ATTNO;   // aliases hwin (dead after QKV GEMMs)
    float* proj  = sc + OFF_PROJ;    // aliases q slab (dead after attention)
    float* h1    = sc + OFF_H1;
    float* mlp1  = sc + OFF_MLP1;
    float* mlp2  = sc + OFF_MLP2;

    // relative-position bias table (depends on cpb weights -> every call)
    cpb_kernel<<<(169 * NHD + 255) / 256, 256>>>(cpb_w0, cpb_b0, cpb_w1);
    rpb_kernel<<<(NHD * NTK * NTK + 255) / 256, 256>>>();

    // shift + window gather
    gather_kernel<<<(MROWS * 48) / 256, 256>>>((const float4*)x, (float4*)hwin);

    // QKV projections (epilogue scatters to [win][head][n][d] per mat slab)
    dim3 gq(CC / GBN, MROWS / GBM);   // 3 x 784
    gemm_kernel<EPI_QKV><<<gq, 256>>>(hwin, q_w, q_b,    qkv,             CC, CC);
    gemm_kernel<EPI_QKV><<<gq, 256>>>(hwin, k_w, nullptr, qkv + (size_t)TOKF,      CC, CC);
    gemm_kernel<EPI_QKV><<<gq, 256>>>(hwin, v_w, v_b,    qkv + 2ull * TOKF, CC, CC);

    // cosine-sim normalize q and k (first two slabs, contiguous)
    normqk_kernel<<<(2 * NWIN * NHD * NTK) / 8, 256>>>(qkv);

    // windowed attention (writes merged-head rows; attno aliases hwin)
    attn_kernel<<<NWIN * NHD, 256>>>(qkv, lscale, attno);

    // output projection + window-reverse + reverse-shift scatter
    // (proj aliases the q slab; attn only reads q before this point)
    gemm_kernel<EPI_PROJ><<<gq, 256>>>(attno, proj_w, proj_b, proj, CC, CC);

    // h1 = x + LN(attn_out)
    ln_res_kernel<<<MROWS / 8, 256>>>(x, proj, ln1_g, ln1_b, h1);

    // MLP
    dim3 g1(HID / GBN, MROWS / GBM);  // 12 x 784
    gemm_kernel<EPI_GELU><<<g1, 256>>>(h1, fc1_w, fc1_b, mlp1, HID, CC);
    gemm_kernel<EPI_PLAIN><<<gq, 256>>>(mlp1, fc2_w, fc2_b, mlp2, CC, HID);

    // out = h1 + LN(mlp)
    ln_res_kernel<<<MROWS / 8, 256>>>(h1, mlp2, ln2_g, ln2_b, out);
}

// round 7
// speedup vs baseline: 1.1569x; 1.1569x over previous
#include <cuda_runtime.h>
#include <math.h>
#include <stdint.h>

// ---------------------------------------------------------------------------
// Problem constants
// ---------------------------------------------------------------------------
#define BATCH   8
#define HH      112
#define CC      192
#define WS      7
#define SHIFT   3
#define NHD     6
#define HDIM    32
#define NTK     49            // WS*WS
#define NWIN    2048          // BATCH * 16 * 16
#define MROWS   100352        // NWIN * NTK
#define LTOK    12544         // HH*HH
#define HID     768           // 4*C
#define TOKF    19267584      // MROWS*CC (one activation slab, floats)
#define LOG100F 4.6051701859880914f

// ---------------------------------------------------------------------------
// Scratch: ONE static device slab, manually partitioned (allocation-free).
//   [0*TOKF)            hwin      (dead after QKV)   -- aliased by attno
//   [1*TOKF .. 4*TOKF)  qkv q|k|v (q-slab dead after attn) -- q aliased by proj
//   [4*TOKF)            h1
//   [5*TOKF .. 9*TOKF)  mlp1 (MROWS*HID)
//   [9*TOKF)            mlp2
// ---------------------------------------------------------------------------
__device__ float g_scratch[10ull * TOKF];
__device__ float g_cpb[169 * NHD];
__device__ float g_rpb[NHD * NTK * NTK];
__device__ float g_wqkv[CC * 3 * CC];     // packed [k][n] n: q|k|v  (192 x 576)
__device__ float g_bqkv[3 * CC];

#define OFF_HWIN  (0ull * TOKF)
#define OFF_QKV   (1ull * TOKF)
#define OFF_ATTNO (0ull * TOKF)
#define OFF_PROJ  (1ull * TOKF)
#define OFF_H1    (4ull * TOKF)
#define OFF_MLP1  (5ull * TOKF)
#define OFF_MLP2  (9ull * TOKF)

// ---------------------------------------------------------------------------
// CPB MLP: 169 relative offsets -> 16*sigmoid(relu(t@w0+b0)@w1)
// ---------------------------------------------------------------------------
__device__ __forceinline__ float rel_coord(int a) {
    float ch = (float)(a - (WS - 1));
    float t  = ch / (float)(WS - 1) * 8.0f;
    float v  = log2f(fabsf(t) + 1.0f) / log2f(8.0f);
    return (t > 0.f) ? v : ((t < 0.f) ? -v : 0.f);
}

__global__ void cpb_kernel(const float* __restrict__ w0, const float* __restrict__ b0,
                           const float* __restrict__ w1) {
    int idx = blockIdx.x * blockDim.x + threadIdx.x;
    if (idx >= 169 * NHD) return;
    int t = idx / NHD, h = idx % NHD;
    float c0 = rel_coord(t / 13);
    float c1 = rel_coord(t % 13);
    float s = 0.f;
    for (int j = 0; j < 512; ++j) {
        float hid = fmaf(c0, w0[j], fmaf(c1, w0[512 + j], b0[j]));
        hid = fmaxf(hid, 0.f);
        s = fmaf(hid, w1[j * NHD + h], s);
    }
    g_cpb[idx] = 16.0f / (1.0f + expf(-s));
}

__global__ void rpb_kernel() {
    int idx = blockIdx.x * blockDim.x + threadIdx.x;
    if (idx >= NHD * NTK * NTK) return;
    int h = idx / (NTK * NTK), e = idx % (NTK * NTK);
    int i = e / NTK, j = e % NTK;
    int r0 = i / WS - j / WS + (WS - 1);
    int r1 = i % WS - j % WS + (WS - 1);
    g_rpb[idx] = g_cpb[(r0 * 13 + r1) * NHD + h];
}

// ---------------------------------------------------------------------------
// Pack q|k|v weights into one [192][576] matrix + fused bias (k bias = 0)
// ---------------------------------------------------------------------------
__global__ void packw_kernel(const float* __restrict__ q_w, const float* __restrict__ q_b,
                             const float* __restrict__ k_w, const float* __restrict__ v_w,
                             const float* __restrict__ v_b) {
    int idx = blockIdx.x * 256 + threadIdx.x;
    if (idx < CC * 3 * CC) {
        int k = idx / (3 * CC), n = idx % (3 * CC);
        float v = (n < CC) ? q_w[k * CC + n]
                : (n < 2 * CC) ? k_w[k * CC + n - CC]
                : v_w[k * CC + n - 2 * CC];
        g_wqkv[idx] = v;
    }
    if (idx < 3 * CC) {
        g_bqkv[idx] = (idx < CC) ? q_b[idx] : (idx < 2 * CC) ? 0.f : v_b[idx - 2 * CC];
    }
}

// ---------------------------------------------------------------------------
// Shift + window partition gather (float4 wide)
// ---------------------------------------------------------------------------
__global__ void gather_kernel(const float4* __restrict__ x, float4* __restrict__ hwin) {
    int idx = blockIdx.x * 256 + threadIdx.x;                 // over MROWS*48
    if (idx >= MROWS * 48) return;
    int m = idx / 48, c4 = idx % 48;
    int w = m / NTK, n = m % NTK;
    int b = w >> 8, widx = w & 255;
    int wh = widx >> 4, ww = widx & 15;
    int gh = wh * WS + n / WS + SHIFT; if (gh >= HH) gh -= HH;
    int gw = ww * WS + n % WS + SHIFT; if (gw >= HH) gw -= HH;
    hwin[idx] = x[((size_t)(b * LTOK + gh * HH + gw)) * 48 + c4];
}

// ---------------------------------------------------------------------------
// TF32 tensor-core GEMM:  C[M,N] = A[M,K] @ B[K,N] (+bias, epilogue variants)
// 128x64 tile, BK=16, 256 threads (8 warps = 4x2), warp tile 32x32,
// mma.sync.m16n8k8.tf32 with fp32 accum. SPLIT=true -> 3xTF32 (fp32-accurate).
// ---------------------------------------------------------------------------
#define TBM 128
#define TBN 64
#define TBK 16

enum { EPI_PLAIN = 0, EPI_GELU = 1, EPI_PROJ = 2, EPI_QKV = 3 };

__device__ __forceinline__ float gelu_tanh(float x) {
    float x3 = x * x * x;
    return 0.5f * x * (1.0f + tanhf(0.7978845608028654f * (x + 0.044715f * x3)));
}

__device__ __forceinline__ uint32_t f2tf32(float x) {
    uint32_t u;
    asm("cvt.rna.tf32.f32 %0, %1;" : "=r"(u) : "f"(x));
    return u;
}

__device__ __forceinline__ void mma_tf32(float c[4], const uint32_t a[4], const uint32_t b[2]) {
    asm volatile(
        "mma.sync.aligned.m16n8k8.row.col.f32.tf32.tf32.f32 "
        "{%0,%1,%2,%3}, {%4,%5,%6,%7}, {%8,%9}, {%0,%1,%2,%3};\n"
        : "+f"(c[0]), "+f"(c[1]), "+f"(c[2]), "+f"(c[3])
        : "r"(a[0]), "r"(a[1]), "r"(a[2]), "r"(a[3]), "r"(b[0]), "r"(b[1]));
}

template <int EPI, bool SPLIT>
__global__ __launch_bounds__(256) void gemm_tc(
    const float* __restrict__ A, const float* __restrict__ Bm,
    const float* __restrict__ bias, float* __restrict__ Cout,
    int Nn, int K)
{
    __shared__ uint32_t AsH[TBK][TBM + 4];
    __shared__ uint32_t BsH[TBK][TBN + 4];
    __shared__ uint32_t AsL[SPLIT ? TBK : 1][SPLIT ? TBM + 4 : 1];
    __shared__ uint32_t BsL[SPLIT ? TBK : 1][SPLIT ? TBN + 4 : 1];

    int tid  = threadIdx.x;
    int lane = tid & 31;
    int wrp  = tid >> 5;
    int warpM = wrp >> 1;        // 0..3
    int warpN = wrp & 1;         // 0..1
    int gr = lane >> 2;          // group row 0..7
    int tc = lane & 3;           // thread-in-group 0..3
    int bm = blockIdx.y, bn = blockIdx.x;

    const float* Aptr = A + (size_t)bm * TBM * K;
    const float* Bptr = Bm + (size_t)bn * TBN;

    // global-load coords
    int aIdx0 = tid * 2;                 // two float4 of A per thread
    int aRow0 = aIdx0 >> 2, aKc0 = (aIdx0 & 3) * 4;
    int aRow1 = (aIdx0 + 1) >> 2, aKc1 = ((aIdx0 + 1) & 3) * 4;
    int bK = tid >> 4, bN = (tid & 15) * 4;  // one float4 of B per thread

    float acc[2][4][4];
#pragma unroll
    for (int mi = 0; mi < 2; ++mi)
#pragma unroll
        for (int ni = 0; ni < 4; ++ni)
#pragma unroll
            for (int e = 0; e < 4; ++e) acc[mi][ni][e] = 0.f;

    int iters = K / TBK;
    float4 av0 = *(const float4*)(Aptr + (size_t)aRow0 * K + aKc0);
    float4 av1 = *(const float4*)(Aptr + (size_t)aRow1 * K + aKc1);
    float4 bv  = *(const float4*)(Bptr + (size_t)bK * Nn + bN);

    for (int it = 0; it < iters; ++it) {
        // store staged tile to smem (with tf32 conversion / split)
        {
            float a4[2][4] = {{av0.x, av0.y, av0.z, av0.w}, {av1.x, av1.y, av1.z, av1.w}};
            int rows[2] = {aRow0, aRow1}, kcs[2] = {aKc0, aKc1};
#pragma unroll
            for (int q = 0; q < 2; ++q)
#pragma unroll
                for (int e = 0; e < 4; ++e) {
                    float v = a4[q][e];
                    uint32_t hi = f2tf32(v);
                    AsH[kcs[q] + e][rows[q]] = hi;
                    if constexpr (SPLIT)
                        AsL[kcs[q] + e][rows[q]] = f2tf32(v - __uint_as_float(hi));
                }
            float b4[4] = {bv.x, bv.y, bv.z, bv.w};
#pragma unroll
            for (int e = 0; e < 4; ++e) {
                float v = b4[e];
                uint32_t hi = f2tf32(v);
                BsH[bK][bN + e] = hi;
                if constexpr (SPLIT)
                    BsL[bK][bN + e] = f2tf32(v - __uint_as_float(hi));
            }
        }
        __syncthreads();

        // prefetch next tile
        if (it + 1 < iters) {
            int k0 = (it + 1) * TBK;
            av0 = *(const float4*)(Aptr + (size_t)aRow0 * K + k0 + aKc0);
            av1 = *(const float4*)(Aptr + (size_t)aRow1 * K + k0 + aKc1);
            bv  = *(const float4*)(Bptr + (size_t)(k0 + bK) * Nn + bN);
        }

        // mma over the tile: 2 k8-steps
#pragma unroll
        for (int ks = 0; ks < 2; ++ks) {
            int kb = ks * 8;
            uint32_t aH[2][4], bH[4][2];
#pragma unroll
            for (int mi = 0; mi < 2; ++mi) {
                int r0 = warpM * 32 + mi * 16;
                aH[mi][0] = AsH[kb + tc][r0 + gr];
                aH[mi][1] = AsH[kb + tc][r0 + gr + 8];
                aH[mi][2] = AsH[kb + tc + 4][r0 + gr];
                aH[mi][3] = AsH[kb + tc + 4][r0 + gr + 8];
            }
#pragma unroll
            for (int ni = 0; ni < 4; ++ni) {
                int c0 = warpN * 32 + ni * 8 + gr;
                bH[ni][0] = BsH[kb + tc][c0];
                bH[ni][1] = BsH[kb + tc + 4][c0];
            }
            if constexpr (SPLIT) {
                uint32_t aL[2][4], bL[4][2];
#pragma unroll
                for (int mi = 0; mi < 2; ++mi) {
                    int r0 = warpM * 32 + mi * 16;
                    aL[mi][0] = AsL[kb + tc][r0 + gr];
                    aL[mi][1] = AsL[kb + tc][r0 + gr + 8];
                    aL[mi][2] = AsL[kb + tc + 4][r0 + gr];
                    aL[mi][3] = AsL[kb + tc + 4][r0 + gr + 8];
                }
#pragma unroll
                for (int ni = 0; ni < 4; ++ni) {
                    int c0 = warpN * 32 + ni * 8 + gr;
                    bL[ni][0] = BsL[kb + tc][c0];
                    bL[ni][1] = BsL[kb + tc + 4][c0];
                }
#pragma unroll
                for (int mi = 0; mi < 2; ++mi)
#pragma unroll
                    for (int ni = 0; ni < 4; ++ni) {
                        mma_tf32(acc[mi][ni], aH[mi], bL[ni]);
                        mma_tf32(acc[mi][ni], aL[mi], bH[ni]);
                        mma_tf32(acc[mi][ni], aH[mi], bH[ni]);
                    }
            } else {
#pragma unroll
                for (int mi = 0; mi < 2; ++mi)
#pragma unroll
                    for (int ni = 0; ni < 4; ++ni)
                        mma_tf32(acc[mi][ni], aH[mi], bH[ni]);
            }
        }
        __syncthreads();
    }

    // epilogue
#pragma unroll
    for (int mi = 0; mi < 2; ++mi) {
        int rbase = bm * TBM + warpM * 32 + mi * 16 + gr;
#pragma unroll
        for (int ni = 0; ni < 4; ++ni) {
            int cbase = bn * TBN + warpN * 32 + ni * 8 + 2 * tc;
#pragma unroll
            for (int e = 0; e < 4; ++e) {
                int row = rbase + (e >> 1) * 8;
                int col = cbase + (e & 1);
                float v = acc[mi][ni][e];
                if constexpr (EPI == EPI_PLAIN) {
                    Cout[(size_t)row * Nn + col] = v + bias[col];
                } else if constexpr (EPI == EPI_GELU) {
                    Cout[(size_t)row * Nn + col] = gelu_tanh(v + bias[col]);
                } else if constexpr (EPI == EPI_PROJ) {
                    v += bias[col];
                    int w = row / NTK, n = row % NTK;
                    int b = w >> 8, widx = w & 255;
                    int wh = widx >> 4, ww = widx & 15;
                    int gh = wh * WS + n / WS + SHIFT; if (gh >= HH) gh -= HH;
                    int gw = ww * WS + n % WS + SHIFT; if (gw >= HH) gw -= HH;
                    Cout[((size_t)(b * LTOK + gh * HH + gw)) * CC + col] = v;
                } else {  // EPI_QKV: col in [0,576); mat = col/192
                    v += bias[col];
                    int mat = col / CC, c = col - mat * CC;
                    int head = c >> 5, d = c & 31;
                    int w = row / NTK, n = row % NTK;
                    size_t off = (size_t)mat * TOKF +
                                 (((size_t)w * NHD + head) * NTK + n) * HDIM + d;
                    Cout[off] = v;
                }
            }
        }
    }
}

// ---------------------------------------------------------------------------
// L2-normalize q,k rows (32 elems each) : 1 warp per row
// ---------------------------------------------------------------------------
__global__ void normqk_kernel(float* __restrict__ qk) {
    int row = blockIdx.x * 8 + (threadIdx.x >> 5);
    int lane = threadIdx.x & 31;
    float* p = qk + (size_t)row * HDIM;
    float v = p[lane];
    float ss = v * v;
#pragma unroll
    for (int o = 16; o; o >>= 1) ss += __shfl_xor_sync(0xffffffffu, ss, o);
    float sc = 1.0f / fmaxf(sqrtf(ss), 1e-6f);
    p[lane] = v * sc;
}

// ---------------------------------------------------------------------------
// Attention: 1 block per (window, head). smem q/kT/v + scores; softmax; PV.
// ---------------------------------------------------------------------------
__global__ __launch_bounds__(256) void attn_kernel(
    const float* __restrict__ qkv, const float* __restrict__ logit_scale,
    float* __restrict__ out)
{
    __shared__ float sq[NTK * HDIM];
    __shared__ float skT[HDIM * 50];
    __shared__ float sv[NTK * HDIM];
    __shared__ float sS[NTK * 50];

    int bid = blockIdx.x;
    int w = bid / NHD, hd = bid % NHD;
    size_t base = ((size_t)w * NHD + hd) * (NTK * HDIM);
    const float* qp = qkv + base;
    const float* kp = qkv + (size_t)TOKF + base;
    const float* vp = qkv + 2ull * TOKF + base;

    int tid = threadIdx.x;
    for (int i = tid; i < NTK * HDIM; i += 256) {
        sq[i] = qp[i];
        sv[i] = vp[i];
        int r = i >> 5, t = i & 31;
        skT[t * 50 + r] = kp[i];
    }
    float scale = expf(fminf(logit_scale[hd], LOG100F));
    int widx = w & 255;
    int wh = widx >> 4, ww = widx & 15;
    __syncthreads();

    for (int e = tid; e < NTK * NTK; e += 256) {
        int i = e / NTK, j = e % NTK;
        float s = 0.f;
#pragma unroll 8
        for (int t = 0; t < HDIM; ++t) s = fmaf(sq[i * HDIM + t], skT[t * 50 + j], s);
        int hi = wh * WS + i / WS, wi = ww * WS + i % WS;
        int hj = wh * WS + j / WS, wj = ww * WS + j % WS;
        int idi = (hi < 105 ? 0 : (hi < 109 ? 1 : 2)) * 3 + (wi < 105 ? 0 : (wi < 109 ? 1 : 2));
        int idj = (hj < 105 ? 0 : (hj < 109 ? 1 : 2)) * 3 + (wj < 105 ? 0 : (wj < 109 ? 1 : 2));
        s = fmaf(s, scale, g_rpb[hd * (NTK * NTK) + e]);
        if (idi != idj) s -= 100.0f;
        sS[i * 50 + j] = s;
    }
    __syncthreads();

    int wid = tid >> 5, lane = tid & 31;
    for (int r = wid; r < NTK; r += 8) {
        float v0 = sS[r * 50 + lane];
        float v1 = (lane + 32 < NTK) ? sS[r * 50 + lane + 32] : -3.4e38f;
        float m = fmaxf(v0, v1);
#pragma unroll
        for (int o = 16; o; o >>= 1) m = fmaxf(m, __shfl_xor_sync(0xffffffffu, m, o));
        float e0 = expf(v0 - m);
        float e1 = (lane + 32 < NTK) ? expf(v1 - m) : 0.f;
        float s = e0 + e1;
#pragma unroll
        for (int o = 16; o; o >>= 1) s += __shfl_xor_sync(0xffffffffu, s, o);
        float inv = 1.0f / s;
        sS[r * 50 + lane] = e0 * inv;
        if (lane + 32 < NTK) sS[r * 50 + lane + 32] = e1 * inv;
    }
    __syncthreads();

    for (int e = tid; e < NTK * HDIM; e += 256) {
        int i = e >> 5, d = e & 31;
        float acc = 0.f;
#pragma unroll
        for (int j = 0; j < NTK; ++j) acc = fmaf(sS[i * 50 + j], sv[j * HDIM + d], acc);
        out[((size_t)w * NTK + i) * CC + hd * HDIM + d] = acc;
    }
}

// ---------------------------------------------------------------------------
// out = res + LayerNorm(v) * g + b   (1 warp / row of 192)
// ---------------------------------------------------------------------------
__global__ void ln_res_kernel(const float* __restrict__ res, const float* __restrict__ v,
                              const float* __restrict__ g, const float* __restrict__ bb,
                              float* __restrict__ out) {
    int row = blockIdx.x * 8 + (threadIdx.x >> 5);
    int lane = threadIdx.x & 31;
    const float* vp = v + (size_t)row * CC;
    float x[6];
    float s = 0.f;
#pragma unroll
    for (int t = 0; t < 6; ++t) { x[t] = vp[lane + 32 * t]; s += x[t]; }
#pragma unroll
    for (int o = 16; o; o >>= 1) s += __shfl_xor_sync(0xffffffffu, s, o);
    float mean = s * (1.0f / CC);
    float q = 0.f;
#pragma unroll
    for (int t = 0; t < 6; ++t) { float d = x[t] - mean; q += d * d; }
#pragma unroll
    for (int o = 16; o; o >>= 1) q += __shfl_xor_sync(0xffffffffu, q, o);
    float rstd = rsqrtf(q * (1.0f / CC) + 1e-5f);
#pragma unroll
    for (int t = 0; t < 6; ++t) {
        int c = lane + 32 * t;
        out[(size_t)row * CC + c] = res[(size_t)row * CC + c] + (x[t] - mean) * rstd * g[c] + bb[c];
    }
}

// ---------------------------------------------------------------------------
// Launch
// ---------------------------------------------------------------------------
extern "C" void kernel_launch(void* const* d_in, const int* in_sizes, int n_in,
                              void* d_out, int out_size) {
    const float* x      = (const float*)d_in[0];
    const float* q_w    = (const float*)d_in[1];
    const float* q_b    = (const float*)d_in[2];
    const float* k_w    = (const float*)d_in[3];
    const float* v_w    = (const float*)d_in[4];
    const float* v_b    = (const float*)d_in[5];
    const float* proj_w = (const float*)d_in[6];
    const float* proj_b = (const float*)d_in[7];
    const float* lscale = (const float*)d_in[8];
    const float* cpb_w0 = (const float*)d_in[9];
    const float* cpb_b0 = (const float*)d_in[10];
    const float* cpb_w1 = (const float*)d_in[11];
    const float* ln1_g  = (const float*)d_in[12];
    const float* ln1_b  = (const float*)d_in[13];
    const float* ln2_g  = (const float*)d_in[14];
    const float* ln2_b  = (const float*)d_in[15];
    const float* fc1_w  = (const float*)d_in[16];
    const float* fc1_b  = (const float*)d_in[17];
    const float* fc2_w  = (const float*)d_in[18];
    const float* fc2_b  = (const float*)d_in[19];
    float* out = (float*)d_out;

    void* p;
    cudaGetSymbolAddress(&p, g_scratch);
    float* sc    = (float*)p;
    float* hwin  = sc + OFF_HWIN;
    float* qkv   = sc + OFF_QKV;
    float* attno = sc + OFF_ATTNO;
    float* proj  = sc + OFF_PROJ;
    float* h1    = sc + OFF_H1;
    float* mlp1  = sc + OFF_MLP1;
    float* mlp2  = sc + OFF_MLP2;
    cudaGetSymbolAddress(&p, g_wqkv);
    float* wqkv = (float*)p;
    cudaGetSymbolAddress(&p, g_bqkv);
    float* bqkv = (float*)p;

    // relative-position bias table + packed QKV weights
    cpb_kernel<<<(169 * NHD + 255) / 256, 256>>>(cpb_w0, cpb_b0, cpb_w1);
    rpb_kernel<<<(NHD * NTK * NTK + 255) / 256, 256>>>();
    packw_kernel<<<(CC * 3 * CC + 255) / 256, 256>>>(q_w, q_b, k_w, v_w, v_b);

    // shift + window gather
    gather_kernel<<<(MROWS * 48) / 256, 256>>>((const float4*)x, (float4*)hwin);

    // Fused QKV projection: [MROWS,192] @ [192,576], 3xTF32 (fp32-accurate),
    // epilogue scatters to [mat][win][head][n][d]
    dim3 gqkv(3 * CC / TBN, MROWS / TBM);   // 9 x 784
    gemm_tc<EPI_QKV, true><<<gqkv, 256>>>(hwin, wqkv, bqkv, qkv, 3 * CC, CC);

    // cosine-sim normalize q and k (first two slabs, contiguous)
    normqk_kernel<<<(2 * NWIN * NHD * NTK) / 8, 256>>>(qkv);

    // windowed attention (fp32; writes merged-head rows; attno aliases hwin)
    attn_kernel<<<NWIN * NHD, 256>>>(qkv, lscale, attno);

    // output projection (3xTF32: feeds both residual branches) + reverse-shift scatter
    dim3 gq(CC / TBN, MROWS / TBM);         // 3 x 784
    gemm_tc<EPI_PROJ, true><<<gq, 256>>>(attno, proj_w, proj_b, proj, CC, CC);

    // h1 = x + LN(attn_out)
    ln_res_kernel<<<MROWS / 8, 256>>>(x, proj, ln1_g, ln1_b, h1);

    // MLP (1xTF32)
    dim3 g1(HID / TBN, MROWS / TBM);        // 12 x 784
    gemm_tc<EPI_GELU, false><<<g1, 256>>>(h1, fc1_w, fc1_b, mlp1, HID, CC);
    gemm_tc<EPI_PLAIN, false><<<gq, 256>>>(mlp1, fc2_w, fc2_b, mlp2, CC, HID);

    // out = h1 + LN(mlp)
    ln_res_kernel<<<MROWS / 8, 256>>>(h1, mlp2, ln2_g, ln2_b, out);
}

// round 8
// speedup vs baseline: 1.3713x; 1.1854x over previous
#include <cuda_runtime.h>
#include <cuda_bf16.h>
#include <math.h>
#include <stdint.h>

// ---------------------------------------------------------------------------
// Problem constants
// ---------------------------------------------------------------------------
#define BATCH   8
#define HH      112
#define CC      192
#define WS      7
#define SHIFT   3
#define NHD     6
#define HDIM    32
#define NTK     49            // WS*WS
#define NWIN    2048          // BATCH * 16 * 16
#define MROWS   100352        // NWIN * NTK
#define LTOK    12544         // HH*HH
#define HID     768           // 4*C
#define TOKF    19267584      // MROWS*CC (one activation slab, floats)
#define LOG100F 4.6051701859880914f

// ---------------------------------------------------------------------------
// Scratch: ONE static device slab, manually partitioned (allocation-free).
// ---------------------------------------------------------------------------
__device__ float g_scratch[10ull * TOKF];
__device__ float g_cpb[169 * NHD];
__device__ float g_rpb[NHD * NTK * NTK];
__device__ float g_wqkv[CC * 3 * CC];     // packed [k][n] n: q|k|v  (192 x 576)
__device__ float g_bqkv[3 * CC];

#define OFF_HWIN  (0ull * TOKF)
#define OFF_QKV   (1ull * TOKF)
#define OFF_ATTNO (0ull * TOKF)
#define OFF_PROJ  (1ull * TOKF)
#define OFF_H1    (4ull * TOKF)
#define OFF_MLP1  (5ull * TOKF)
#define OFF_MLP2  (9ull * TOKF)

// ---------------------------------------------------------------------------
// CPB MLP: 169 relative offsets -> 16*sigmoid(relu(t@w0+b0)@w1)
// ---------------------------------------------------------------------------
__device__ __forceinline__ float rel_coord(int a) {
    float ch = (float)(a - (WS - 1));
    float t  = ch / (float)(WS - 1) * 8.0f;
    float v  = log2f(fabsf(t) + 1.0f) / log2f(8.0f);
    return (t > 0.f) ? v : ((t < 0.f) ? -v : 0.f);
}

__global__ void cpb_kernel(const float* __restrict__ w0, const float* __restrict__ b0,
                           const float* __restrict__ w1) {
    int idx = blockIdx.x * blockDim.x + threadIdx.x;
    if (idx >= 169 * NHD) return;
    int t = idx / NHD, h = idx % NHD;
    float c0 = rel_coord(t / 13);
    float c1 = rel_coord(t % 13);
    float s = 0.f;
    for (int j = 0; j < 512; ++j) {
        float hid = fmaf(c0, w0[j], fmaf(c1, w0[512 + j], b0[j]));
        hid = fmaxf(hid, 0.f);
        s = fmaf(hid, w1[j * NHD + h], s);
    }
    g_cpb[idx] = 16.0f / (1.0f + expf(-s));
}

__global__ void rpb_kernel() {
    int idx = blockIdx.x * blockDim.x + threadIdx.x;
    if (idx >= NHD * NTK * NTK) return;
    int h = idx / (NTK * NTK), e = idx % (NTK * NTK);
    int i = e / NTK, j = e % NTK;
    int r0 = i / WS - j / WS + (WS - 1);
    int r1 = i % WS - j % WS + (WS - 1);
    g_rpb[idx] = g_cpb[(r0 * 13 + r1) * NHD + h];
}

// ---------------------------------------------------------------------------
// Pack q|k|v weights into one [192][576] matrix + fused bias (k bias = 0)
// ---------------------------------------------------------------------------
__global__ void packw_kernel(const float* __restrict__ q_w, const float* __restrict__ q_b,
                             const float* __restrict__ k_w, const float* __restrict__ v_w,
                             const float* __restrict__ v_b) {
    int idx = blockIdx.x * 256 + threadIdx.x;
    if (idx < CC * 3 * CC) {
        int k = idx / (3 * CC), n = idx % (3 * CC);
        float v = (n < CC) ? q_w[k * CC + n]
                : (n < 2 * CC) ? k_w[k * CC + n - CC]
                : v_w[k * CC + n - 2 * CC];
        g_wqkv[idx] = v;
    }
    if (idx < 3 * CC) {
        g_bqkv[idx] = (idx < CC) ? q_b[idx] : (idx < 2 * CC) ? 0.f : v_b[idx - 2 * CC];
    }
}

// ---------------------------------------------------------------------------
// Shift + window partition gather (float4 wide)
// ---------------------------------------------------------------------------
__global__ void gather_kernel(const float4* __restrict__ x, float4* __restrict__ hwin) {
    int idx = blockIdx.x * 256 + threadIdx.x;                 // over MROWS*48
    if (idx >= MROWS * 48) return;
    int m = idx / 48, c4 = idx % 48;
    int w = m / NTK, n = m % NTK;
    int b = w >> 8, widx = w & 255;
    int wh = widx >> 4, ww = widx & 15;
    int gh = wh * WS + n / WS + SHIFT; if (gh >= HH) gh -= HH;
    int gw = ww * WS + n % WS + SHIFT; if (gw >= HH) gw -= HH;
    hwin[idx] = x[((size_t)(b * LTOK + gh * HH + gw)) * 48 + c4];
}

// ---------------------------------------------------------------------------
// bf16 3-term-split tensor-core GEMM (fp32-in fp32-out, ~16 mantissa bits):
//   C = Ahi*Blo + Alo*Bhi + Ahi*Bhi  via mma.sync.m16n8k16.bf16, fp32 accum.
// 128x64 tile, BK=16, 256 threads (8 warps = 4x2), warp tile 32x32.
// Two-stage smem double buffer, one __syncthreads per k-tile.
// smem layout [k-pair][m/n] with strides 136/72 (conflict-free frag reads).
// ---------------------------------------------------------------------------
#define TBM 128
#define TBN 64
#define GBK 16
#define ASTR 136
#define BSTR 72

enum { EPI_PLAIN = 0, EPI_GELU = 1, EPI_PROJ = 2, EPI_QKV = 3 };

__device__ __forceinline__ float gelu_tanh(float x) {
    float x3 = x * x * x;
    return 0.5f * x * (1.0f + tanhf(0.7978845608028654f * (x + 0.044715f * x3)));
}

__device__ __forceinline__ void splitpair(float v0, float v1, uint32_t& hi, uint32_t& lo) {
    __nv_bfloat16 h0 = __float2bfloat16_rn(v0);
    __nv_bfloat16 h1 = __float2bfloat16_rn(v1);
    __nv_bfloat16 l0 = __float2bfloat16_rn(v0 - __bfloat162float(h0));
    __nv_bfloat16 l1 = __float2bfloat16_rn(v1 - __bfloat162float(h1));
    hi = (uint32_t)__bfloat16_as_ushort(h0) | ((uint32_t)__bfloat16_as_ushort(h1) << 16);
    lo = (uint32_t)__bfloat16_as_ushort(l0) | ((uint32_t)__bfloat16_as_ushort(l1) << 16);
}

__device__ __forceinline__ void mma_bf16(float c[4], const uint32_t a[4], const uint32_t b[2]) {
    asm volatile(
        "mma.sync.aligned.m16n8k16.row.col.f32.bf16.bf16.f32 "
        "{%0,%1,%2,%3}, {%4,%5,%6,%7}, {%8,%9}, {%0,%1,%2,%3};\n"
        : "+f"(c[0]), "+f"(c[1]), "+f"(c[2]), "+f"(c[3])
        : "r"(a[0]), "r"(a[1]), "r"(a[2]), "r"(a[3]), "r"(b[0]), "r"(b[1]));
}

template <int EPI>
__global__ __launch_bounds__(256) void gemm_bf3(
    const float* __restrict__ A, const float* __restrict__ Bm,
    const float* __restrict__ bias, float* __restrict__ Cout,
    int Nn, int K)
{
    // [stage][k-pair 0..7][m or n], packed (k,k+1) bf16 pairs
    __shared__ uint32_t AsH[2][8][ASTR];
    __shared__ uint32_t AsL[2][8][ASTR];
    __shared__ uint32_t BsH[2][8][BSTR];
    __shared__ uint32_t BsL[2][8][BSTR];

    int tid  = threadIdx.x;
    int lane = tid & 31;
    int wrp  = tid >> 5;
    int warpM = wrp >> 1;        // 0..3
    int warpN = wrp & 1;         // 0..1
    int gr = lane >> 2;          // 0..7
    int tc = lane & 3;           // 0..3
    int bm = blockIdx.y, bn = blockIdx.x;

    // A loader: thread t -> row (t>>1), k-halves 8*(t&1) .. +7 (two float4)
    int am = tid >> 1, ab = tid & 1;
    const float* Ap = A + ((size_t)bm * TBM + am) * K + 8 * ab;
    // B loader: thread t -> col (t&63), k-pairs (t>>6) and (t>>6)+4
    int bnn = tid & 63, kh = tid >> 6;
    const float* Bp = Bm + (size_t)bn * TBN + bnn;

    float acc[2][4][4];
#pragma unroll
    for (int mi = 0; mi < 2; ++mi)
#pragma unroll
        for (int ni = 0; ni < 4; ++ni)
#pragma unroll
            for (int e = 0; e < 4; ++e) acc[mi][ni][e] = 0.f;

    float4 ra0, ra1;
    float rb0, rb1, rb2, rb3;

    auto LOAD = [&](int k0) {
        ra0 = *(const float4*)(Ap + k0);
        ra1 = *(const float4*)(Ap + k0 + 4);
        rb0 = Bp[(size_t)(k0 + 2 * kh)     * Nn];
        rb1 = Bp[(size_t)(k0 + 2 * kh + 1) * Nn];
        rb2 = Bp[(size_t)(k0 + 2 * kh + 8) * Nn];
        rb3 = Bp[(size_t)(k0 + 2 * kh + 9) * Nn];
    };
    auto STORE = [&](int s) {
        int p0 = 4 * ab;
        uint32_t h, l;
        splitpair(ra0.x, ra0.y, h, l); AsH[s][p0    ][am] = h; AsL[s][p0    ][am] = l;
        splitpair(ra0.z, ra0.w, h, l); AsH[s][p0 + 1][am] = h; AsL[s][p0 + 1][am] = l;
        splitpair(ra1.x, ra1.y, h, l); AsH[s][p0 + 2][am] = h; AsL[s][p0 + 2][am] = l;
        splitpair(ra1.z, ra1.w, h, l); AsH[s][p0 + 3][am] = h; AsL[s][p0 + 3][am] = l;
        splitpair(rb0, rb1, h, l);     BsH[s][kh    ][bnn] = h; BsL[s][kh    ][bnn] = l;
        splitpair(rb2, rb3, h, l);     BsH[s][kh + 4][bnn] = h; BsL[s][kh + 4][bnn] = l;
    };
    auto COMP = [&](int s) {
        uint32_t aH[2][4], aL[2][4], bH[4][2], bL[4][2];
#pragma unroll
        for (int mi = 0; mi < 2; ++mi) {
            int r0 = warpM * 32 + mi * 16 + gr;
            aH[mi][0] = AsH[s][tc    ][r0];     aH[mi][1] = AsH[s][tc    ][r0 + 8];
            aH[mi][2] = AsH[s][tc + 4][r0];     aH[mi][3] = AsH[s][tc + 4][r0 + 8];
            aL[mi][0] = AsL[s][tc    ][r0];     aL[mi][1] = AsL[s][tc    ][r0 + 8];
            aL[mi][2] = AsL[s][tc + 4][r0];     aL[mi][3] = AsL[s][tc + 4][r0 + 8];
        }
#pragma unroll
        for (int ni = 0; ni < 4; ++ni) {
            int c0 = warpN * 32 + ni * 8 + gr;
            bH[ni][0] = BsH[s][tc][c0];         bH[ni][1] = BsH[s][tc + 4][c0];
            bL[ni][0] = BsL[s][tc][c0];         bL[ni][1] = BsL[s][tc + 4][c0];
        }
#pragma unroll
        for (int mi = 0; mi < 2; ++mi)
#pragma unroll
            for (int ni = 0; ni < 4; ++ni) {
                mma_bf16(acc[mi][ni], aH[mi], bL[ni]);
                mma_bf16(acc[mi][ni], aL[mi], bH[ni]);
                mma_bf16(acc[mi][ni], aH[mi], bH[ni]);
            }
    };

    int iters = K / GBK;
    LOAD(0);
    STORE(0);
    __syncthreads();
    for (int it = 0; it < iters; ++it) {
        int cur = it & 1;
        if (it + 1 < iters) LOAD((it + 1) * GBK);
        COMP(cur);
        if (it + 1 < iters) STORE(cur ^ 1);
        __syncthreads();
    }

    // epilogue
#pragma unroll
    for (int mi = 0; mi < 2; ++mi) {
        int rbase = bm * TBM + warpM * 32 + mi * 16 + gr;
#pragma unroll
        for (int ni = 0; ni < 4; ++ni) {
            int cbase = bn * TBN + warpN * 32 + ni * 8 + 2 * tc;
#pragma unroll
            for (int e = 0; e < 4; ++e) {
                int row = rbase + (e >> 1) * 8;
                int col = cbase + (e & 1);
                float v = acc[mi][ni][e];
                if constexpr (EPI == EPI_PLAIN) {
                    Cout[(size_t)row * Nn + col] = v + bias[col];
                } else if constexpr (EPI == EPI_GELU) {
                    Cout[(size_t)row * Nn + col] = gelu_tanh(v + bias[col]);
                } else if constexpr (EPI == EPI_PROJ) {
                    v += bias[col];
                    int w = row / NTK, n = row % NTK;
                    int b = w >> 8, widx = w & 255;
                    int wh = widx >> 4, ww = widx & 15;
                    int gh = wh * WS + n / WS + SHIFT; if (gh >= HH) gh -= HH;
                    int gw = ww * WS + n % WS + SHIFT; if (gw >= HH) gw -= HH;
                    Cout[((size_t)(b * LTOK + gh * HH + gw)) * CC + col] = v;
                } else {  // EPI_QKV: col in [0,576); mat = col/192
                    v += bias[col];
                    int mat = col / CC, c = col - mat * CC;
                    int head = c >> 5, d = c & 31;
                    int w = row / NTK, n = row % NTK;
                    size_t off = (size_t)mat * TOKF +
                                 (((size_t)w * NHD + head) * NTK + n) * HDIM + d;
                    Cout[off] = v;
                }
            }
        }
    }
}

// ---------------------------------------------------------------------------
// L2-normalize q,k rows (32 elems each) : 1 warp per row
// ---------------------------------------------------------------------------
__global__ void normqk_kernel(float* __restrict__ qk) {
    int row = blockIdx.x * 8 + (threadIdx.x >> 5);
    int lane = threadIdx.x & 31;
    float* p = qk + (size_t)row * HDIM;
    float v = p[lane];
    float ss = v * v;
#pragma unroll
    for (int o = 16; o; o >>= 1) ss += __shfl_xor_sync(0xffffffffu, ss, o);
    float sc = 1.0f / fmaxf(sqrtf(ss), 1e-6f);
    p[lane] = v * sc;
}

// ---------------------------------------------------------------------------
// Attention: 1 block per (window, head). smem q/kT/v + scores; softmax; PV.
// ---------------------------------------------------------------------------
__global__ __launch_bounds__(256) void attn_kernel(
    const float* __restrict__ qkv, const float* __restrict__ logit_scale,
    float* __restrict__ out)
{
    __shared__ float sq[NTK * HDIM];
    __shared__ float skT[HDIM * 50];
    __shared__ float sv[NTK * HDIM];
    __shared__ float sS[NTK * 50];

    int bid = blockIdx.x;
    int w = bid / NHD, hd = bid % NHD;
    size_t base = ((size_t)w * NHD + hd) * (NTK * HDIM);
    const float* qp = qkv + base;
    const float* kp = qkv + (size_t)TOKF + base;
    const float* vp = qkv + 2ull * TOKF + base;

    int tid = threadIdx.x;
    for (int i = tid; i < NTK * HDIM; i += 256) {
        sq[i] = qp[i];
        sv[i] = vp[i];
        int r = i >> 5, t = i & 31;
        skT[t * 50 + r] = kp[i];
    }
    float scale = expf(fminf(logit_scale[hd], LOG100F));
    int widx = w & 255;
    int wh = widx >> 4, ww = widx & 15;
    __syncthreads();

    for (int e = tid; e < NTK * NTK; e += 256) {
        int i = e / NTK, j = e % NTK;
        float s = 0.f;
#pragma unroll 8
        for (int t = 0; t < HDIM; ++t) s = fmaf(sq[i * HDIM + t], skT[t * 50 + j], s);
        int hi = wh * WS + i / WS, wi = ww * WS + i % WS;
        int hj = wh * WS + j / WS, wj = ww * WS + j % WS;
        int idi = (hi < 105 ? 0 : (hi < 109 ? 1 : 2)) * 3 + (wi < 105 ? 0 : (wi < 109 ? 1 : 2));
        int idj = (hj < 105 ? 0 : (hj < 109 ? 1 : 2)) * 3 + (wj < 105 ? 0 : (wj < 109 ? 1 : 2));
        s = fmaf(s, scale, g_rpb[hd * (NTK * NTK) + e]);
        if (idi != idj) s -= 100.0f;
        sS[i * 50 + j] = s;
    }
    __syncthreads();

    int wid = tid >> 5, lane = tid & 31;
    for (int r = wid; r < NTK; r += 8) {
        float v0 = sS[r * 50 + lane];
        float v1 = (lane + 32 < NTK) ? sS[r * 50 + lane + 32] : -3.4e38f;
        float m = fmaxf(v0, v1);
#pragma unroll
        for (int o = 16; o; o >>= 1) m = fmaxf(m, __shfl_xor_sync(0xffffffffu, m, o));
        float e0 = expf(v0 - m);
        float e1 = (lane + 32 < NTK) ? expf(v1 - m) : 0.f;
        float s = e0 + e1;
#pragma unroll
        for (int o = 16; o; o >>= 1) s += __shfl_xor_sync(0xffffffffu, s, o);
        float inv = 1.0f / s;
        sS[r * 50 + lane] = e0 * inv;
        if (lane + 32 < NTK) sS[r * 50 + lane + 32] = e1 * inv;
    }
    __syncthreads();

    for (int e = tid; e < NTK * HDIM; e += 256) {
        int i = e >> 5, d = e & 31;
        float acc = 0.f;
#pragma unroll
        for (int j = 0; j < NTK; ++j) acc = fmaf(sS[i * 50 + j], sv[j * HDIM + d], acc);
        out[((size_t)w * NTK + i) * CC + hd * HDIM + d] = acc;
    }
}

// ---------------------------------------------------------------------------
// out = res + LayerNorm(v) * g + b   (1 warp / row of 192)
// ---------------------------------------------------------------------------
__global__ void ln_res_kernel(const float* __restrict__ res, const float* __restrict__ v,
                              const float* __restrict__ g, const float* __restrict__ bb,
                              float* __restrict__ out) {
    int row = blockIdx.x * 8 + (threadIdx.x >> 5);
    int lane = threadIdx.x & 31;
    const float* vp = v + (size_t)row * CC;
    float x[6];
    float s = 0.f;
#pragma unroll
    for (int t = 0; t < 6; ++t) { x[t] = vp[lane + 32 * t]; s += x[t]; }
#pragma unroll
    for (int o = 16; o; o >>= 1) s += __shfl_xor_sync(0xffffffffu, s, o);
    float mean = s * (1.0f / CC);
    float q = 0.f;
#pragma unroll
    for (int t = 0; t < 6; ++t) { float d = x[t] - mean; q += d * d; }
#pragma unroll
    for (int o = 16; o; o >>= 1) q += __shfl_xor_sync(0xffffffffu, q, o);
    float rstd = rsqrtf(q * (1.0f / CC) + 1e-5f);
#pragma unroll
    for (int t = 0; t < 6; ++t) {
        int c = lane + 32 * t;
        out[(size_t)row * CC + c] = res[(size_t)row * CC + c] + (x[t] - mean) * rstd * g[c] + bb[c];
    }
}

// ---------------------------------------------------------------------------
// Launch
// ---------------------------------------------------------------------------
extern "C" void kernel_launch(void* const* d_in, const int* in_sizes, int n_in,
                              void* d_out, int out_size) {
    const float* x      = (const float*)d_in[0];
    const float* q_w    = (const float*)d_in[1];
    const float* q_b    = (const float*)d_in[2];
    const float* k_w    = (const float*)d_in[3];
    const float* v_w    = (const float*)d_in[4];
    const float* v_b    = (const float*)d_in[5];
    const float* proj_w = (const float*)d_in[6];
    const float* proj_b = (const float*)d_in[7];
    const float* lscale = (const float*)d_in[8];
    const float* cpb_w0 = (const float*)d_in[9];
    const float* cpb_b0 = (const float*)d_in[10];
    const float* cpb_w1 = (const float*)d_in[11];
    const float* ln1_g  = (const float*)d_in[12];
    const float* ln1_b  = (const float*)d_in[13];
    const float* ln2_g  = (const float*)d_in[14];
    const float* ln2_b  = (const float*)d_in[15];
    const float* fc1_w  = (const float*)d_in[16];
    const float* fc1_b  = (const float*)d_in[17];
    const float* fc2_w  = (const float*)d_in[18];
    const float* fc2_b  = (const float*)d_in[19];
    float* out = (float*)d_out;

    void* p;
    cudaGetSymbolAddress(&p, g_scratch);
    float* sc    = (float*)p;
    float* hwin  = sc + OFF_HWIN;
    float* qkv   = sc + OFF_QKV;
    float* attno = sc + OFF_ATTNO;
    float* proj  = sc + OFF_PROJ;
    float* h1    = sc + OFF_H1;
    float* mlp1  = sc + OFF_MLP1;
    float* mlp2  = sc + OFF_MLP2;
    cudaGetSymbolAddress(&p, g_wqkv);
    float* wqkv = (float*)p;
    cudaGetSymbolAddress(&p, g_bqkv);
    float* bqkv = (float*)p;

    // relative-position bias table + packed QKV weights
    cpb_kernel<<<(169 * NHD + 255) / 256, 256>>>(cpb_w0, cpb_b0, cpb_w1);
    rpb_kernel<<<(NHD * NTK * NTK + 255) / 256, 256>>>();
    packw_kernel<<<(CC * 3 * CC + 255) / 256, 256>>>(q_w, q_b, k_w, v_w, v_b);

    // shift + window gather
    gather_kernel<<<(MROWS * 48) / 256, 256>>>((const float4*)x, (float4*)hwin);

    // Fused QKV projection: [MROWS,192] @ [192,576], bf16 3-term split,
    // epilogue scatters to [mat][win][head][n][d]
    dim3 gqkv(3 * CC / TBN, MROWS / TBM);   // 9 x 784
    gemm_bf3<EPI_QKV><<<gqkv, 256>>>(hwin, wqkv, bqkv, qkv, 3 * CC, CC);

    // cosine-sim normalize q and k (first two slabs, contiguous)
    normqk_kernel<<<(2 * NWIN * NHD * NTK) / 8, 256>>>(qkv);

    // windowed attention (fp32; writes merged-head rows; attno aliases hwin)
    attn_kernel<<<NWIN * NHD, 256>>>(qkv, lscale, attno);

    // output projection + window-reverse + reverse-shift scatter
    dim3 gq(CC / TBN, MROWS / TBM);         // 3 x 784
    gemm_bf3<EPI_PROJ><<<gq, 256>>>(attno, proj_w, proj_b, proj, CC, CC);

    // h1 = x + LN(attn_out)
    ln_res_kernel<<<MROWS / 8, 256>>>(x, proj, ln1_g, ln1_b, h1);

    // MLP
    dim3 g1(HID / TBN, MROWS / TBM);        // 12 x 784
    gemm_bf3<EPI_GELU><<<g1, 256>>>(h1, fc1_w, fc1_b, mlp1, HID, CC);
    gemm_bf3<EPI_PLAIN><<<gq, 256>>>(mlp1, fc2_w, fc2_b, mlp2, CC, HID);

    // out = h1 + LN(mlp)
    ln_res_kernel<<<MROWS / 8, 256>>>(h1, mlp2, ln2_g, ln2_b, out);
}